// round 13
// baseline (speedup 1.0000x reference)
#include <cuda_runtime.h>
#include <math.h>

#define Bn 2
#define Cn 21
#define Hn 512
#define Wn 512
#define HL 128
#define WL 128
#define Kn 11
#define SPANn 5
#define KKn 121

#define PP 144
#define XOFF 5
#define YOFF 8
#define PLANE (PP*PP)

#define GK_TILE 64

__device__ float g_ppad [Bn*Cn*PLANE];
__device__ float g_msg  [Bn*Cn*HL*WL];
__device__ float g_cf   [Bn*3*HL*WL];
__device__ float g_gk   [Bn*16*16*KKn*GK_TILE];   // per 8x8 tile

__constant__ float c_wtab[4] = {0.375f, 0.125f, 0.875f, 0.625f};

// ---------------------------------------------------------------------------
__global__ void k_zero() {
    int idx = blockIdx.x * 256 + threadIdx.x;
    if (idx < Bn*Cn*PLANE/4) ((float4*)g_ppad)[idx] = make_float4(0.f,0.f,0.f,0.f);
}

// ---------------------------------------------------------------------------
__global__ void k_pool_img(const float* __restrict__ img, const float* __restrict__ schan) {
    int idx = blockIdx.x * 256 + threadIdx.x;
    if (idx >= Bn*3*HL*WL) return;
    int y = idx & (WL-1);
    int x = (idx >> 7) & (HL-1);
    int c = (idx >> 14) % 3;
    int b = idx / (3*HL*WL);
    const float* src = img + ((b*3 + c)*Hn + x*4)*Wn + y*4;
    float s = 0.f;
    #pragma unroll
    for (int i = 0; i < 4; i++)
        #pragma unroll
        for (int j = 0; j < 4; j++) s += src[i*Wn + j];
    g_cf[idx] = s * (schan[0] * 0.0625f);
}

// ---------------------------------------------------------------------------
// gauss kernel, tiled per 8x8 pixel block: [b][txi][tyi][ij][64]
__global__ void k_gauss(const float* __restrict__ pos_sdims,
                        const float* __restrict__ pos_compat,
                        const float* __restrict__ col_compat) {
    __shared__ float cf_s[3][18*18];
    __shared__ float pos_s[KKn];
    int tyi = blockIdx.x, txi = blockIdx.y, b = blockIdx.z;
    int t = threadIdx.x;
    int x0 = txi*8 - SPANn, y0 = tyi*8 - SPANn;
    for (int i = t; i < KKn; i += 64) {
        int ii = i / 11, j = i - ii*11;
        int dx = ii - SPANn, dy = j - SPANn;
        float sd4 = 4.f * pos_sdims[0];
        float dpos2 = sd4*sd4 * (float)(dx*dx + dy*dy);
        pos_s[i] = pos_compat[0] * __expf(-0.5f*dpos2);
    }
    for (int i = t; i < 3*324; i += 64) {
        int c = i / 324, rem = i % 324;
        int xx = x0 + rem/18, yy = y0 + rem%18;
        float v = 0.f;
        if ((unsigned)xx < HL && (unsigned)yy < WL)
            v = g_cf[((b*3 + c)*HL + xx)*WL + yy];
        cf_s[c][rem] = v;
    }
    __syncthreads();
    int px = t >> 3, py = t & 7;
    int ctr = (px + SPANn)*18 + (py + SPANn);
    float c0 = cf_s[0][ctr], c1 = cf_s[1][ctr], c2 = cf_s[2][ctr];
    float cc = col_compat[0];
    int gx = txi*8 + px, gy = tyi*8 + py;
    float* outb = g_gk + (size_t)(((b*16 + txi)*16 + tyi)*KKn)*GK_TILE + t;
    #pragma unroll 1
    for (int ij = 0; ij < KKn; ij++) {
        int i = ij / 11, j = ij - i*11;
        int dx = i - SPANn, dy = j - SPANn;
        bool valid = ((unsigned)(gx + dx) < HL) && ((unsigned)(gy + dy) < WL);
        int si = (px + i)*18 + (py + j);
        float d0 = cf_s[0][si] - c0;
        float d1 = cf_s[1][si] - c1;
        float d2 = cf_s[2][si] - c2;
        float dcol2 = d0*d0 + d1*d1 + d2*d2;
        float gval = valid ? (pos_s[ij] + cc * __expf(-0.5f*dcol2)) : 0.f;
        outb[ij*GK_TILE] = gval;
    }
}

// ---------------------------------------------------------------------------
// 3) pooled init pred (exact R9)
__global__ void k_init(const float* __restrict__ unary) {
    int b = blockIdx.z;
    int w = threadIdx.x >> 5, l = threadIdx.x & 31;
    int x0 = blockIdx.y*32 + w*4;
    int Y  = blockIdx.x*32 + l;
    const float* up = unary + ((size_t)(b*Cn)*Hn + x0)*Wn + Y;
    float pool[Cn];
    #pragma unroll
    for (int c = 0; c < Cn; c++) pool[c] = 0.f;
    #pragma unroll
    for (int r = 0; r < 4; r++) {
        float u[Cn];
        float m = -1e30f;
        #pragma unroll
        for (int c = 0; c < Cn; c++) {
            u[c] = __ldg(up + (size_t)c*Hn*Wn + r*Wn);
            m = fmaxf(m, u[c]);
        }
        float s = 0.f;
        #pragma unroll
        for (int c = 0; c < Cn; c++) s += __expf(u[c] - m);
        float lse = m + logf(s);
        #pragma unroll
        for (int c = 0; c < Cn; c++) pool[c] += u[c] - lse;
    }
    int xp = (x0 >> 2) + XOFF;
    int yp = (Y  >> 2) + YOFF;
    #pragma unroll
    for (int c = 0; c < Cn; c++) {
        float r = pool[c];
        r += __shfl_xor_sync(0xffffffffu, r, 1);
        r += __shfl_xor_sync(0xffffffffu, r, 2);
        if ((l & 3) == 0)
            g_ppad[((size_t)(b*Cn + c)*PP + xp)*PP + yp] = r * 0.0625f;
    }
}

// ---------------------------------------------------------------------------
// 4) message passing: 8x8 tile, 31KB static smem, 512 blocks, 224 threads.
//    thread = 3 channels (chunk) x 2 pixels (lane: 8 xrows x 4 col-pairs)
__global__ __launch_bounds__(224) void k_msg() {
    __shared__ float gk_s[KKn*GK_TILE];
    const int t = threadIdx.x;
    const int b = blockIdx.z;
    const int tyi = blockIdx.x, txi = blockIdx.y;
    const int chunk = t >> 5, lane = t & 31;
    const int xrow = lane >> 2, yg = lane & 3;
    const int pxg = txi*8 + xrow;
    const int Yb  = tyi*8 + yg*2;
    const float* gbase = g_gk + (size_t)(((b*16 + txi)*16 + tyi)*KKn)*GK_TILE;

    {
        const float4* src = (const float4*)gbase;
        #pragma unroll 3
        for (int idx = t; idx < KKn*16; idx += 224)
            ((float4*)gk_s)[idx] = __ldg(src + idx);
    }
    __syncthreads();

    float acc[3][2];
    #pragma unroll
    for (int c = 0; c < 3; c++) { acc[c][0] = 0.f; acc[c][1] = 0.f; }

    const int pix = xrow*8 + yg*2;
    const int A   = (Yb + 3) & ~3;      // aligned load base (padded col)
    const int rel = (Yb + 3) & 3;       // window start within pr

    #pragma unroll 1
    for (int i = 0; i < 11; i++) {
        float pr[3][16];
        #pragma unroll
        for (int c = 0; c < 3; c++) {
            const float4* pp = (const float4*)(g_ppad +
                ((size_t)(b*Cn + chunk*3 + c)*PP + (pxg + i))*PP + A);
            #pragma unroll
            for (int q = 0; q < 4; q++) {
                float4 v = __ldg(pp + q);
                pr[c][q*4+0] = v.x; pr[c][q*4+1] = v.y;
                pr[c][q*4+2] = v.z; pr[c][q*4+3] = v.w;
            }
        }
        const float* gs = gk_s + i*11*GK_TILE + pix;
        #pragma unroll
        for (int j = 0; j < 11; j++) {
            float2 gv = *(const float2*)(gs + j*GK_TILE);
            #pragma unroll
            for (int c = 0; c < 3; c++) {
                acc[c][0] += gv.x * pr[c][rel + j];
                acc[c][1] += gv.y * pr[c][rel + j + 1];
            }
        }
    }

    #pragma unroll
    for (int c = 0; c < 3; c++) {
        float* mp = g_msg + ((size_t)(b*Cn + chunk*3 + c)*HL + pxg)*WL + Yb;
        *(float2*)mp = make_float2(acc[c][0], acc[c][1]);
    }
}

// ---------------------------------------------------------------------------
// 5) fused iter (exact R9)
__global__ void k_iter(const float* __restrict__ unary, const float* __restrict__ weight) {
    __shared__ float m_s[Cn*100];   // [c][10][10]
    int b = blockIdx.z;
    int t = threadIdx.x, w = t >> 5, l = t & 31;
    int lx0 = blockIdx.y*8 - 1, ly0 = blockIdx.x*8 - 1;
    for (int i = t; i < Cn*100; i += 256) {
        int c = i / 100, rem = i % 100;
        int xx = lx0 + rem/10; xx = max(0, min(HL-1, xx));
        int yy = ly0 + rem%10; yy = max(0, min(WL-1, yy));
        m_s[i] = g_msg[((b*Cn + c)*HL + xx)*WL + yy];
    }
    __syncthreads();
    int x0 = blockIdx.y*32 + w*4;
    int Y  = blockIdx.x*32 + l;
    const float* up = unary + ((size_t)(b*Cn)*Hn + x0)*Wn + Y;
    float wgt = weight[0], uw = 1.f - wgt;
    int ry = l & 3;
    float wy0 = c_wtab[ry], wy1 = 1.f - wy0;
    int yA = (l >> 2) + 1 + ((ry < 2) ? -1 : 0);
    float pool[Cn];
    #pragma unroll
    for (int c = 0; c < Cn; c++) pool[c] = 0.f;
    #pragma unroll
    for (int r = 0; r < 4; r++) {
        float wx0 = c_wtab[r], wx1 = 1.f - wx0;
        int xA = w + 1 + ((r < 2) ? -1 : 0);
        int base = xA*10 + yA;
        float v[Cn];
        float mmax = -1e30f;
        #pragma unroll
        for (int c = 0; c < Cn; c++) {
            const float* mc = m_s + c*100 + base;
            float mu = wx0*(wy0*mc[0] + wy1*mc[1]) + wx1*(wy0*mc[10] + wy1*mc[11]);
            float vv = uw * __ldg(up + (size_t)c*Hn*Wn + r*Wn) + wgt * mu;
            v[c] = vv;
            mmax = fmaxf(mmax, vv);
        }
        float s = 0.f;
        #pragma unroll
        for (int c = 0; c < Cn; c++) { v[c] = __expf(v[c] - mmax); s += v[c]; }
        float inv = 1.f / s;
        #pragma unroll
        for (int c = 0; c < Cn; c++) pool[c] += v[c] * inv;
    }
    int xp = (x0 >> 2) + XOFF;
    int yp = (Y  >> 2) + YOFF;
    #pragma unroll
    for (int c = 0; c < Cn; c++) {
        float r = pool[c];
        r += __shfl_xor_sync(0xffffffffu, r, 1);
        r += __shfl_xor_sync(0xffffffffu, r, 2);
        if ((l & 3) == 0)
            g_ppad[((size_t)(b*Cn + c)*PP + xp)*PP + yp] = r * 0.0625f;
    }
}

// ---------------------------------------------------------------------------
// 6) final (exact R9)
__global__ void k_final(const float* __restrict__ unary, const float* __restrict__ weight,
                        float* __restrict__ out) {
    __shared__ float m_s[Cn*100];
    int b = blockIdx.z;
    int t = threadIdx.x, w = t >> 5, l = t & 31;
    int lx0 = blockIdx.y*8 - 1, ly0 = blockIdx.x*8 - 1;
    for (int i = t; i < Cn*100; i += 256) {
        int c = i / 100, rem = i % 100;
        int xx = lx0 + rem/10; xx = max(0, min(HL-1, xx));
        int yy = ly0 + rem%10; yy = max(0, min(WL-1, yy));
        m_s[i] = g_msg[((b*Cn + c)*HL + xx)*WL + yy];
    }
    __syncthreads();
    int x0 = blockIdx.y*32 + w*4;
    int Y  = blockIdx.x*32 + l;
    const float* up   = unary + ((size_t)(b*Cn)*Hn + x0)*Wn + Y;
    float*       outp = out   + ((size_t)(b*Cn)*Hn + x0)*Wn + Y;
    float wgt = weight[0], uw = 1.f - wgt;
    int ry = l & 3;
    float wy0 = c_wtab[ry], wy1 = 1.f - wy0;
    int yA = (l >> 2) + 1 + ((ry < 2) ? -1 : 0);
    #pragma unroll
    for (int r = 0; r < 4; r++) {
        float wx0 = c_wtab[r], wx1 = 1.f - wx0;
        int xA = w + 1 + ((r < 2) ? -1 : 0);
        int base = xA*10 + yA;
        float u[Cn];
        float m = -1e30f;
        #pragma unroll
        for (int c = 0; c < Cn; c++) {
            u[c] = __ldg(up + (size_t)c*Hn*Wn + r*Wn);
            m = fmaxf(m, u[c]);
        }
        float s = 0.f;
        #pragma unroll
        for (int c = 0; c < Cn; c++) s += __expf(u[c] - m);
        float lse = m + logf(s);
        #pragma unroll
        for (int c = 0; c < Cn; c++) {
            const float* mc = m_s + c*100 + base;
            float mu = wx0*(wy0*mc[0] + wy1*mc[1]) + wx1*(wy0*mc[10] + wy1*mc[11]);
            outp[(size_t)c*Hn*Wn + r*Wn] = uw * (u[c] - lse) + wgt * mu;
        }
    }
}

// ---------------------------------------------------------------------------
extern "C" void kernel_launch(void* const* d_in, const int* in_sizes, int n_in,
                              void* d_out, int out_size) {
    const float* unary      = (const float*)d_in[0];
    const float* img        = (const float*)d_in[1];
    const float* pos_sdims  = (const float*)d_in[2];
    const float* col_schan  = (const float*)d_in[3];
    const float* pos_compat = (const float*)d_in[4];
    const float* col_compat = (const float*)d_in[5];
    const float* weight     = (const float*)d_in[6];
    float* out = (float*)d_out;

    k_zero<<<(Bn*Cn*PLANE/4 + 255)/256, 256>>>();
    k_pool_img<<<(Bn*3*HL*WL + 255)/256, 256>>>(img, col_schan);
    k_gauss<<<dim3(16, 16, Bn), 64>>>(pos_sdims, pos_compat, col_compat);
    k_init<<<dim3(16, 16, Bn), 256>>>(unary);
    for (int it = 0; it < 5; it++) {
        k_msg<<<dim3(16, 16, Bn), 224>>>();
        if (it < 4)
            k_iter<<<dim3(16, 16, Bn), 256>>>(unary, weight);
        else
            k_final<<<dim3(16, 16, Bn), 256>>>(unary, weight, out);
    }
}

// round 14
// speedup vs baseline: 1.9144x; 1.9144x over previous
#include <cuda_runtime.h>
#include <math.h>

#define Bn 2
#define Cn 21
#define Hn 512
#define Wn 512
#define HL 128
#define WL 128
#define Kn 11
#define SPANn 5
#define KKn 121

#define PP 144
#define XOFF 5
#define YOFF 8
#define PLANE (PP*PP)

#define GK_TILE 128
#define GK_SMEM_BYTES (KKn * GK_TILE * 4)

__device__ float g_ppad [Bn*Cn*PLANE];
__device__ float g_msg  [Bn*Cn*HL*WL];
__device__ float g_cf   [Bn*3*HL*WL];
__device__ float g_gk   [Bn*16*8*KKn*GK_TILE];

__constant__ float c_wtab[4] = {0.375f, 0.125f, 0.875f, 0.625f};

// ---------------------------------------------------------------------------
__global__ void k_zero() {
    int idx = blockIdx.x * 256 + threadIdx.x;
    if (idx < Bn*Cn*PLANE/4) ((float4*)g_ppad)[idx] = make_float4(0.f,0.f,0.f,0.f);
}

// ---------------------------------------------------------------------------
__global__ void k_pool_img(const float* __restrict__ img, const float* __restrict__ schan) {
    int idx = blockIdx.x * 256 + threadIdx.x;
    if (idx >= Bn*3*HL*WL) return;
    int y = idx & (WL-1);
    int x = (idx >> 7) & (HL-1);
    int c = (idx >> 14) % 3;
    int b = idx / (3*HL*WL);
    const float* src = img + ((b*3 + c)*Hn + x*4)*Wn + y*4;
    float s = 0.f;
    #pragma unroll
    for (int i = 0; i < 4; i++)
        #pragma unroll
        for (int j = 0; j < 4; j++) s += src[i*Wn + j];
    g_cf[idx] = s * (schan[0] * 0.0625f);
}

// ---------------------------------------------------------------------------
// gauss kernel, tiled per 8x16 pixel block (exact R9)
__global__ void k_gauss(const float* __restrict__ pos_sdims,
                        const float* __restrict__ pos_compat,
                        const float* __restrict__ col_compat) {
    __shared__ float cf_s[3][18*26];
    __shared__ float pos_s[KKn];
    int tyi = blockIdx.x, txi = blockIdx.y, b = blockIdx.z;
    int t = threadIdx.x;
    int x0 = txi*8 - SPANn, y0 = tyi*16 - SPANn;
    if (t < KKn) {
        int i = t / 11, j = t - i*11;
        int dx = i - SPANn, dy = j - SPANn;
        float sd4 = 4.f * pos_sdims[0];
        float dpos2 = sd4*sd4 * (float)(dx*dx + dy*dy);
        pos_s[t] = pos_compat[0] * __expf(-0.5f*dpos2);
    }
    for (int i = t; i < 3*468; i += 128) {
        int c = i / 468, rem = i % 468;
        int xx = x0 + rem/26, yy = y0 + rem%26;
        float v = 0.f;
        if ((unsigned)xx < HL && (unsigned)yy < WL)
            v = g_cf[((b*3 + c)*HL + xx)*WL + yy];
        cf_s[c][rem] = v;
    }
    __syncthreads();
    int px = t >> 4, py = t & 15;
    int ctr = (px + SPANn)*26 + (py + SPANn);
    float c0 = cf_s[0][ctr], c1 = cf_s[1][ctr], c2 = cf_s[2][ctr];
    float cc = col_compat[0];
    int gx = txi*8 + px, gy = tyi*16 + py;
    float* outb = g_gk + (size_t)(((b*16 + txi)*8 + tyi)*KKn)*GK_TILE + t;
    #pragma unroll 1
    for (int ij = 0; ij < KKn; ij++) {
        int i = ij / 11, j = ij - i*11;
        int dx = i - SPANn, dy = j - SPANn;
        bool valid = ((unsigned)(gx + dx) < HL) && ((unsigned)(gy + dy) < WL);
        int si = (px + i)*26 + (py + j);
        float d0 = cf_s[0][si] - c0;
        float d1 = cf_s[1][si] - c1;
        float d2 = cf_s[2][si] - c2;
        float dcol2 = d0*d0 + d1*d1 + d2*d2;
        float gval = valid ? (pos_s[ij] + cc * __expf(-0.5f*dcol2)) : 0.f;
        outb[ij*GK_TILE] = gval;
    }
}

// ---------------------------------------------------------------------------
// 3) pooled init pred (exact R9)
__global__ void k_init(const float* __restrict__ unary) {
    int b = blockIdx.z;
    int w = threadIdx.x >> 5, l = threadIdx.x & 31;
    int x0 = blockIdx.y*32 + w*4;
    int Y  = blockIdx.x*32 + l;
    const float* up = unary + ((size_t)(b*Cn)*Hn + x0)*Wn + Y;
    float pool[Cn];
    #pragma unroll
    for (int c = 0; c < Cn; c++) pool[c] = 0.f;
    #pragma unroll
    for (int r = 0; r < 4; r++) {
        float u[Cn];
        float m = -1e30f;
        #pragma unroll
        for (int c = 0; c < Cn; c++) {
            u[c] = __ldg(up + (size_t)c*Hn*Wn + r*Wn);
            m = fmaxf(m, u[c]);
        }
        float s = 0.f;
        #pragma unroll
        for (int c = 0; c < Cn; c++) s += __expf(u[c] - m);
        float lse = m + logf(s);
        #pragma unroll
        for (int c = 0; c < Cn; c++) pool[c] += u[c] - lse;
    }
    int xp = (x0 >> 2) + XOFF;
    int yp = (Y  >> 2) + YOFF;
    #pragma unroll
    for (int c = 0; c < Cn; c++) {
        float r = pool[c];
        r += __shfl_xor_sync(0xffffffffu, r, 1);
        r += __shfl_xor_sync(0xffffffffu, r, 2);
        if ((l & 3) == 0)
            g_ppad[((size_t)(b*Cn + c)*PP + xp)*PP + yp] = r * 0.0625f;
    }
}

// ---------------------------------------------------------------------------
// 4) message passing: 8x16 tile, 62KB smem, 384 threads = 12 warps.
//    chunk = t>>5 owns up to 2 channels; lane = 8 xrows x 4 col-groups of 4.
__global__ __launch_bounds__(384) void k_msg() {
    extern __shared__ float gk_s[];           // [121][128]
    const int t = threadIdx.x;
    const int b = blockIdx.z;
    const int tyi = blockIdx.x, txi = blockIdx.y;
    const int chunk = t >> 5, lane = t & 31;
    const int xrow = lane >> 2, yg = lane & 3;
    const int pxg = txi*8 + xrow;
    const int Yb  = tyi*16 + yg*4;
    const int c0 = min(2*chunk, 20), c1 = min(2*chunk + 1, 20);
    const bool s0 = (2*chunk)     < Cn;
    const bool s1 = (2*chunk + 1) < Cn;
    const float* gbase = g_gk + (size_t)(((b*16 + txi)*8 + tyi)*KKn)*GK_TILE;

    {
        const float4* src = (const float4*)gbase;
        #pragma unroll 4
        for (int idx = t; idx < KKn*32; idx += 384)
            ((float4*)gk_s)[idx] = __ldg(src + idx);
    }
    __syncthreads();

    float acc[2][4];
    #pragma unroll
    for (int c = 0; c < 2; c++)
        #pragma unroll
        for (int k = 0; k < 4; k++) acc[c][k] = 0.f;

    const int pix = lane*4;
    #pragma unroll 1
    for (int i = 0; i < 11; i++) {
        float pr[2][20];
        #pragma unroll
        for (int c = 0; c < 2; c++) {
            int ch = c ? c1 : c0;
            const float4* pp = (const float4*)(g_ppad +
                ((size_t)(b*Cn + ch)*PP + (pxg + i))*PP + Yb);
            #pragma unroll
            for (int q = 0; q < 5; q++) {
                float4 v = __ldg(pp + q);
                pr[c][q*4+0] = v.x; pr[c][q*4+1] = v.y;
                pr[c][q*4+2] = v.z; pr[c][q*4+3] = v.w;
            }
        }
        const float* gs = gk_s + i*11*GK_TILE + pix;
        #pragma unroll
        for (int j = 0; j < 11; j++) {
            float4 gv = *(const float4*)(gs + j*GK_TILE);
            #pragma unroll
            for (int c = 0; c < 2; c++) {
                acc[c][0] += gv.x * pr[c][0 + j + 3];
                acc[c][1] += gv.y * pr[c][1 + j + 3];
                acc[c][2] += gv.z * pr[c][2 + j + 3];
                acc[c][3] += gv.w * pr[c][3 + j + 3];
            }
        }
    }

    if (s0) {
        float* mp = g_msg + ((size_t)(b*Cn + c0)*HL + pxg)*WL + Yb;
        *(float4*)mp = make_float4(acc[0][0], acc[0][1], acc[0][2], acc[0][3]);
    }
    if (s1) {
        float* mp = g_msg + ((size_t)(b*Cn + c1)*HL + pxg)*WL + Yb;
        *(float4*)mp = make_float4(acc[1][0], acc[1][1], acc[1][2], acc[1][3]);
    }
}

// ---------------------------------------------------------------------------
// 5) fused iter (exact R9)
__global__ void k_iter(const float* __restrict__ unary, const float* __restrict__ weight) {
    __shared__ float m_s[Cn*100];   // [c][10][10]
    int b = blockIdx.z;
    int t = threadIdx.x, w = t >> 5, l = t & 31;
    int lx0 = blockIdx.y*8 - 1, ly0 = blockIdx.x*8 - 1;
    for (int i = t; i < Cn*100; i += 256) {
        int c = i / 100, rem = i % 100;
        int xx = lx0 + rem/10; xx = max(0, min(HL-1, xx));
        int yy = ly0 + rem%10; yy = max(0, min(WL-1, yy));
        m_s[i] = g_msg[((b*Cn + c)*HL + xx)*WL + yy];
    }
    __syncthreads();
    int x0 = blockIdx.y*32 + w*4;
    int Y  = blockIdx.x*32 + l;
    const float* up = unary + ((size_t)(b*Cn)*Hn + x0)*Wn + Y;
    float wgt = weight[0], uw = 1.f - wgt;
    int ry = l & 3;
    float wy0 = c_wtab[ry], wy1 = 1.f - wy0;
    int yA = (l >> 2) + 1 + ((ry < 2) ? -1 : 0);
    float pool[Cn];
    #pragma unroll
    for (int c = 0; c < Cn; c++) pool[c] = 0.f;
    #pragma unroll
    for (int r = 0; r < 4; r++) {
        float wx0 = c_wtab[r], wx1 = 1.f - wx0;
        int xA = w + 1 + ((r < 2) ? -1 : 0);
        int base = xA*10 + yA;
        float v[Cn];
        float mmax = -1e30f;
        #pragma unroll
        for (int c = 0; c < Cn; c++) {
            const float* mc = m_s + c*100 + base;
            float mu = wx0*(wy0*mc[0] + wy1*mc[1]) + wx1*(wy0*mc[10] + wy1*mc[11]);
            float vv = uw * __ldg(up + (size_t)c*Hn*Wn + r*Wn) + wgt * mu;
            v[c] = vv;
            mmax = fmaxf(mmax, vv);
        }
        float s = 0.f;
        #pragma unroll
        for (int c = 0; c < Cn; c++) { v[c] = __expf(v[c] - mmax); s += v[c]; }
        float inv = 1.f / s;
        #pragma unroll
        for (int c = 0; c < Cn; c++) pool[c] += v[c] * inv;
    }
    int xp = (x0 >> 2) + XOFF;
    int yp = (Y  >> 2) + YOFF;
    #pragma unroll
    for (int c = 0; c < Cn; c++) {
        float r = pool[c];
        r += __shfl_xor_sync(0xffffffffu, r, 1);
        r += __shfl_xor_sync(0xffffffffu, r, 2);
        if ((l & 3) == 0)
            g_ppad[((size_t)(b*Cn + c)*PP + xp)*PP + yp] = r * 0.0625f;
    }
}

// ---------------------------------------------------------------------------
// 6) final (exact R9)
__global__ void k_final(const float* __restrict__ unary, const float* __restrict__ weight,
                        float* __restrict__ out) {
    __shared__ float m_s[Cn*100];
    int b = blockIdx.z;
    int t = threadIdx.x, w = t >> 5, l = t & 31;
    int lx0 = blockIdx.y*8 - 1, ly0 = blockIdx.x*8 - 1;
    for (int i = t; i < Cn*100; i += 256) {
        int c = i / 100, rem = i % 100;
        int xx = lx0 + rem/10; xx = max(0, min(HL-1, xx));
        int yy = ly0 + rem%10; yy = max(0, min(WL-1, yy));
        m_s[i] = g_msg[((b*Cn + c)*HL + xx)*WL + yy];
    }
    __syncthreads();
    int x0 = blockIdx.y*32 + w*4;
    int Y  = blockIdx.x*32 + l;
    const float* up   = unary + ((size_t)(b*Cn)*Hn + x0)*Wn + Y;
    float*       outp = out   + ((size_t)(b*Cn)*Hn + x0)*Wn + Y;
    float wgt = weight[0], uw = 1.f - wgt;
    int ry = l & 3;
    float wy0 = c_wtab[ry], wy1 = 1.f - wy0;
    int yA = (l >> 2) + 1 + ((ry < 2) ? -1 : 0);
    #pragma unroll
    for (int r = 0; r < 4; r++) {
        float wx0 = c_wtab[r], wx1 = 1.f - wx0;
        int xA = w + 1 + ((r < 2) ? -1 : 0);
        int base = xA*10 + yA;
        float u[Cn];
        float m = -1e30f;
        #pragma unroll
        for (int c = 0; c < Cn; c++) {
            u[c] = __ldg(up + (size_t)c*Hn*Wn + r*Wn);
            m = fmaxf(m, u[c]);
        }
        float s = 0.f;
        #pragma unroll
        for (int c = 0; c < Cn; c++) s += __expf(u[c] - m);
        float lse = m + logf(s);
        #pragma unroll
        for (int c = 0; c < Cn; c++) {
            const float* mc = m_s + c*100 + base;
            float mu = wx0*(wy0*mc[0] + wy1*mc[1]) + wx1*(wy0*mc[10] + wy1*mc[11]);
            outp[(size_t)c*Hn*Wn + r*Wn] = uw * (u[c] - lse) + wgt * mu;
        }
    }
}

// ---------------------------------------------------------------------------
extern "C" void kernel_launch(void* const* d_in, const int* in_sizes, int n_in,
                              void* d_out, int out_size) {
    const float* unary      = (const float*)d_in[0];
    const float* img        = (const float*)d_in[1];
    const float* pos_sdims  = (const float*)d_in[2];
    const float* col_schan  = (const float*)d_in[3];
    const float* pos_compat = (const float*)d_in[4];
    const float* col_compat = (const float*)d_in[5];
    const float* weight     = (const float*)d_in[6];
    float* out = (float*)d_out;

    static int smem_set = 0;
    if (!smem_set) {
        cudaFuncSetAttribute(k_msg, cudaFuncAttributeMaxDynamicSharedMemorySize,
                             GK_SMEM_BYTES);
        smem_set = 1;
    }

    k_zero<<<(Bn*Cn*PLANE/4 + 255)/256, 256>>>();
    k_pool_img<<<(Bn*3*HL*WL + 255)/256, 256>>>(img, col_schan);
    k_gauss<<<dim3(8, 16, Bn), 128>>>(pos_sdims, pos_compat, col_compat);
    k_init<<<dim3(16, 16, Bn), 256>>>(unary);
    for (int it = 0; it < 5; it++) {
        k_msg<<<dim3(8, 16, Bn), 384, GK_SMEM_BYTES>>>();
        if (it < 4)
            k_iter<<<dim3(16, 16, Bn), 256>>>(unary, weight);
        else
            k_final<<<dim3(16, 16, Bn), 256>>>(unary, weight, out);
    }
}

// round 15
// speedup vs baseline: 2.0555x; 1.0737x over previous
#include <cuda_runtime.h>
#include <math.h>

#define Bn 2
#define Cn 21
#define Hn 512
#define Wn 512
#define HL 128
#define WL 128
#define Kn 11
#define SPANn 5
#define KKn 121

#define PP 144
#define XOFF 5
#define YOFF 8
#define PLANE (PP*PP)

#define GK_TILE 128
#define GK_SMEM_BYTES (KKn * GK_TILE * 4)

__device__ float g_ppad [Bn*Cn*PLANE];
__device__ float g_msg  [Bn*Cn*HL*WL];
__device__ float g_cf   [Bn*3*HL*WL];
__device__ float g_gk   [Bn*16*8*KKn*GK_TILE];

__constant__ float c_wtab[4] = {0.375f, 0.125f, 0.875f, 0.625f};

// ---------------------------------------------------------------------------
__global__ void k_zero() {
    int idx = blockIdx.x * 256 + threadIdx.x;
    if (idx < Bn*Cn*PLANE/4) ((float4*)g_ppad)[idx] = make_float4(0.f,0.f,0.f,0.f);
}

// ---------------------------------------------------------------------------
__global__ void k_pool_img(const float* __restrict__ img, const float* __restrict__ schan) {
    int idx = blockIdx.x * 256 + threadIdx.x;
    if (idx >= Bn*3*HL*WL) return;
    int y = idx & (WL-1);
    int x = (idx >> 7) & (HL-1);
    int c = (idx >> 14) % 3;
    int b = idx / (3*HL*WL);
    const float* src = img + ((b*3 + c)*Hn + x*4)*Wn + y*4;
    float s = 0.f;
    #pragma unroll
    for (int i = 0; i < 4; i++)
        #pragma unroll
        for (int j = 0; j < 4; j++) s += src[i*Wn + j];
    g_cf[idx] = s * (schan[0] * 0.0625f);
}

// ---------------------------------------------------------------------------
// gauss kernel, tiled per 8x16 pixel block (exact R9)
__global__ void k_gauss(const float* __restrict__ pos_sdims,
                        const float* __restrict__ pos_compat,
                        const float* __restrict__ col_compat) {
    __shared__ float cf_s[3][18*26];
    __shared__ float pos_s[KKn];
    int tyi = blockIdx.x, txi = blockIdx.y, b = blockIdx.z;
    int t = threadIdx.x;
    int x0 = txi*8 - SPANn, y0 = tyi*16 - SPANn;
    if (t < KKn) {
        int i = t / 11, j = t - i*11;
        int dx = i - SPANn, dy = j - SPANn;
        float sd4 = 4.f * pos_sdims[0];
        float dpos2 = sd4*sd4 * (float)(dx*dx + dy*dy);
        pos_s[t] = pos_compat[0] * __expf(-0.5f*dpos2);
    }
    for (int i = t; i < 3*468; i += 128) {
        int c = i / 468, rem = i % 468;
        int xx = x0 + rem/26, yy = y0 + rem%26;
        float v = 0.f;
        if ((unsigned)xx < HL && (unsigned)yy < WL)
            v = g_cf[((b*3 + c)*HL + xx)*WL + yy];
        cf_s[c][rem] = v;
    }
    __syncthreads();
    int px = t >> 4, py = t & 15;
    int ctr = (px + SPANn)*26 + (py + SPANn);
    float c0 = cf_s[0][ctr], c1 = cf_s[1][ctr], c2 = cf_s[2][ctr];
    float cc = col_compat[0];
    int gx = txi*8 + px, gy = tyi*16 + py;
    float* outb = g_gk + (size_t)(((b*16 + txi)*8 + tyi)*KKn)*GK_TILE + t;
    #pragma unroll 1
    for (int ij = 0; ij < KKn; ij++) {
        int i = ij / 11, j = ij - i*11;
        int dx = i - SPANn, dy = j - SPANn;
        bool valid = ((unsigned)(gx + dx) < HL) && ((unsigned)(gy + dy) < WL);
        int si = (px + i)*26 + (py + j);
        float d0 = cf_s[0][si] - c0;
        float d1 = cf_s[1][si] - c1;
        float d2 = cf_s[2][si] - c2;
        float dcol2 = d0*d0 + d1*d1 + d2*d2;
        float gval = valid ? (pos_s[ij] + cc * __expf(-0.5f*dcol2)) : 0.f;
        outb[ij*GK_TILE] = gval;
    }
}

// ---------------------------------------------------------------------------
// 3) pooled init pred (exact R9)
__global__ void k_init(const float* __restrict__ unary) {
    int b = blockIdx.z;
    int w = threadIdx.x >> 5, l = threadIdx.x & 31;
    int x0 = blockIdx.y*32 + w*4;
    int Y  = blockIdx.x*32 + l;
    const float* up = unary + ((size_t)(b*Cn)*Hn + x0)*Wn + Y;
    float pool[Cn];
    #pragma unroll
    for (int c = 0; c < Cn; c++) pool[c] = 0.f;
    #pragma unroll
    for (int r = 0; r < 4; r++) {
        float u[Cn];
        float m = -1e30f;
        #pragma unroll
        for (int c = 0; c < Cn; c++) {
            u[c] = __ldg(up + (size_t)c*Hn*Wn + r*Wn);
            m = fmaxf(m, u[c]);
        }
        float s = 0.f;
        #pragma unroll
        for (int c = 0; c < Cn; c++) s += __expf(u[c] - m);
        float lse = m + logf(s);
        #pragma unroll
        for (int c = 0; c < Cn; c++) pool[c] += u[c] - lse;
    }
    int xp = (x0 >> 2) + XOFF;
    int yp = (Y  >> 2) + YOFF;
    #pragma unroll
    for (int c = 0; c < Cn; c++) {
        float r = pool[c];
        r += __shfl_xor_sync(0xffffffffu, r, 1);
        r += __shfl_xor_sync(0xffffffffu, r, 2);
        if ((l & 3) == 0)
            g_ppad[((size_t)(b*Cn + c)*PP + xp)*PP + yp] = r * 0.0625f;
    }
}

// ---------------------------------------------------------------------------
// 4) message passing: 8x16 tile, 224 thr, SOFTWARE-PIPELINED pr loads.
//    Fully unrolled i-loop, double-buffered raw float4 staging.
__global__ __launch_bounds__(224, 2) void k_msg() {
    extern __shared__ float gk_s[];           // [121][128]
    const int t = threadIdx.x;
    const int b = blockIdx.z;
    const int tyi = blockIdx.x, txi = blockIdx.y;
    const int chunk = t >> 5, lane = t & 31;
    const int xrow = lane >> 2, yg = lane & 3;
    const int pxg = txi*8 + xrow;
    const int Yb  = tyi*16 + yg*4;
    const float* gbase = g_gk + (size_t)(((b*16 + txi)*8 + tyi)*KKn)*GK_TILE;

    {
        const float4* src = (const float4*)gbase;
        #pragma unroll 4
        for (int idx = t; idx < KKn*32; idx += 224)
            ((float4*)gk_s)[idx] = __ldg(src + idx);
    }
    __syncthreads();

    float acc[3][4];
    #pragma unroll
    for (int c = 0; c < 3; c++)
        #pragma unroll
        for (int k = 0; k < 4; k++) acc[c][k] = 0.f;

    const int pix = lane*4;
    const float4* pb[3];
    #pragma unroll
    for (int c = 0; c < 3; c++)
        pb[c] = (const float4*)(g_ppad +
            ((size_t)(b*Cn + chunk*3 + c)*PP + pxg)*PP + Yb);

    float4 st[2][3][5];
    #pragma unroll
    for (int c = 0; c < 3; c++)
        #pragma unroll
        for (int q = 0; q < 5; q++)
            st[0][c][q] = __ldg(pb[c] + q);

    #pragma unroll
    for (int i = 0; i < 11; i++) {
        const int cur = i & 1, nxt = cur ^ 1;
        // prefetch row i+1 (overlaps with this iteration's FMAs)
        if (i < 10) {
            #pragma unroll
            for (int c = 0; c < 3; c++)
                #pragma unroll
                for (int q = 0; q < 5; q++)
                    st[nxt][c][q] = __ldg(pb[c] + (size_t)(i+1)*(PP/4) + q);
        }
        // unpack current buffer (compile-time indices; reg-to-reg)
        float pr[3][20];
        #pragma unroll
        for (int c = 0; c < 3; c++)
            #pragma unroll
            for (int q = 0; q < 5; q++) {
                pr[c][q*4+0] = st[cur][c][q].x;
                pr[c][q*4+1] = st[cur][c][q].y;
                pr[c][q*4+2] = st[cur][c][q].z;
                pr[c][q*4+3] = st[cur][c][q].w;
            }
        const float* gs = gk_s + i*11*GK_TILE + pix;
        #pragma unroll
        for (int j = 0; j < 11; j++) {
            float4 gv = *(const float4*)(gs + j*GK_TILE);
            #pragma unroll
            for (int c = 0; c < 3; c++) {
                acc[c][0] += gv.x * pr[c][j + 3];
                acc[c][1] += gv.y * pr[c][j + 4];
                acc[c][2] += gv.z * pr[c][j + 5];
                acc[c][3] += gv.w * pr[c][j + 6];
            }
        }
    }

    #pragma unroll
    for (int c = 0; c < 3; c++) {
        float* mp = g_msg + ((size_t)(b*Cn + chunk*3 + c)*HL + pxg)*WL + Yb;
        *(float4*)mp = make_float4(acc[c][0], acc[c][1], acc[c][2], acc[c][3]);
    }
}

// ---------------------------------------------------------------------------
// 5) fused iter (exact R9)
__global__ void k_iter(const float* __restrict__ unary, const float* __restrict__ weight) {
    __shared__ float m_s[Cn*100];   // [c][10][10]
    int b = blockIdx.z;
    int t = threadIdx.x, w = t >> 5, l = t & 31;
    int lx0 = blockIdx.y*8 - 1, ly0 = blockIdx.x*8 - 1;
    for (int i = t; i < Cn*100; i += 256) {
        int c = i / 100, rem = i % 100;
        int xx = lx0 + rem/10; xx = max(0, min(HL-1, xx));
        int yy = ly0 + rem%10; yy = max(0, min(WL-1, yy));
        m_s[i] = g_msg[((b*Cn + c)*HL + xx)*WL + yy];
    }
    __syncthreads();
    int x0 = blockIdx.y*32 + w*4;
    int Y  = blockIdx.x*32 + l;
    const float* up = unary + ((size_t)(b*Cn)*Hn + x0)*Wn + Y;
    float wgt = weight[0], uw = 1.f - wgt;
    int ry = l & 3;
    float wy0 = c_wtab[ry], wy1 = 1.f - wy0;
    int yA = (l >> 2) + 1 + ((ry < 2) ? -1 : 0);
    float pool[Cn];
    #pragma unroll
    for (int c = 0; c < Cn; c++) pool[c] = 0.f;
    #pragma unroll
    for (int r = 0; r < 4; r++) {
        float wx0 = c_wtab[r], wx1 = 1.f - wx0;
        int xA = w + 1 + ((r < 2) ? -1 : 0);
        int base = xA*10 + yA;
        float v[Cn];
        float mmax = -1e30f;
        #pragma unroll
        for (int c = 0; c < Cn; c++) {
            const float* mc = m_s + c*100 + base;
            float mu = wx0*(wy0*mc[0] + wy1*mc[1]) + wx1*(wy0*mc[10] + wy1*mc[11]);
            float vv = uw * __ldg(up + (size_t)c*Hn*Wn + r*Wn) + wgt * mu;
            v[c] = vv;
            mmax = fmaxf(mmax, vv);
        }
        float s = 0.f;
        #pragma unroll
        for (int c = 0; c < Cn; c++) { v[c] = __expf(v[c] - mmax); s += v[c]; }
        float inv = 1.f / s;
        #pragma unroll
        for (int c = 0; c < Cn; c++) pool[c] += v[c] * inv;
    }
    int xp = (x0 >> 2) + XOFF;
    int yp = (Y  >> 2) + YOFF;
    #pragma unroll
    for (int c = 0; c < Cn; c++) {
        float r = pool[c];
        r += __shfl_xor_sync(0xffffffffu, r, 1);
        r += __shfl_xor_sync(0xffffffffu, r, 2);
        if ((l & 3) == 0)
            g_ppad[((size_t)(b*Cn + c)*PP + xp)*PP + yp] = r * 0.0625f;
    }
}

// ---------------------------------------------------------------------------
// 6) final (exact R9)
__global__ void k_final(const float* __restrict__ unary, const float* __restrict__ weight,
                        float* __restrict__ out) {
    __shared__ float m_s[Cn*100];
    int b = blockIdx.z;
    int t = threadIdx.x, w = t >> 5, l = t & 31;
    int lx0 = blockIdx.y*8 - 1, ly0 = blockIdx.x*8 - 1;
    for (int i = t; i < Cn*100; i += 256) {
        int c = i / 100, rem = i % 100;
        int xx = lx0 + rem/10; xx = max(0, min(HL-1, xx));
        int yy = ly0 + rem%10; yy = max(0, min(WL-1, yy));
        m_s[i] = g_msg[((b*Cn + c)*HL + xx)*WL + yy];
    }
    __syncthreads();
    int x0 = blockIdx.y*32 + w*4;
    int Y  = blockIdx.x*32 + l;
    const float* up   = unary + ((size_t)(b*Cn)*Hn + x0)*Wn + Y;
    float*       outp = out   + ((size_t)(b*Cn)*Hn + x0)*Wn + Y;
    float wgt = weight[0], uw = 1.f - wgt;
    int ry = l & 3;
    float wy0 = c_wtab[ry], wy1 = 1.f - wy0;
    int yA = (l >> 2) + 1 + ((ry < 2) ? -1 : 0);
    #pragma unroll
    for (int r = 0; r < 4; r++) {
        float wx0 = c_wtab[r], wx1 = 1.f - wx0;
        int xA = w + 1 + ((r < 2) ? -1 : 0);
        int base = xA*10 + yA;
        float u[Cn];
        float m = -1e30f;
        #pragma unroll
        for (int c = 0; c < Cn; c++) {
            u[c] = __ldg(up + (size_t)c*Hn*Wn + r*Wn);
            m = fmaxf(m, u[c]);
        }
        float s = 0.f;
        #pragma unroll
        for (int c = 0; c < Cn; c++) s += __expf(u[c] - m);
        float lse = m + logf(s);
        #pragma unroll
        for (int c = 0; c < Cn; c++) {
            const float* mc = m_s + c*100 + base;
            float mu = wx0*(wy0*mc[0] + wy1*mc[1]) + wx1*(wy0*mc[10] + wy1*mc[11]);
            outp[(size_t)c*Hn*Wn + r*Wn] = uw * (u[c] - lse) + wgt * mu;
        }
    }
}

// ---------------------------------------------------------------------------
extern "C" void kernel_launch(void* const* d_in, const int* in_sizes, int n_in,
                              void* d_out, int out_size) {
    const float* unary      = (const float*)d_in[0];
    const float* img        = (const float*)d_in[1];
    const float* pos_sdims  = (const float*)d_in[2];
    const float* col_schan  = (const float*)d_in[3];
    const float* pos_compat = (const float*)d_in[4];
    const float* col_compat = (const float*)d_in[5];
    const float* weight     = (const float*)d_in[6];
    float* out = (float*)d_out;

    static int smem_set = 0;
    if (!smem_set) {
        cudaFuncSetAttribute(k_msg, cudaFuncAttributeMaxDynamicSharedMemorySize,
                             GK_SMEM_BYTES);
        smem_set = 1;
    }

    k_zero<<<(Bn*Cn*PLANE/4 + 255)/256, 256>>>();
    k_pool_img<<<(Bn*3*HL*WL + 255)/256, 256>>>(img, col_schan);
    k_gauss<<<dim3(8, 16, Bn), 128>>>(pos_sdims, pos_compat, col_compat);
    k_init<<<dim3(16, 16, Bn), 256>>>(unary);
    for (int it = 0; it < 5; it++) {
        k_msg<<<dim3(8, 16, Bn), 224, GK_SMEM_BYTES>>>();
        if (it < 4)
            k_iter<<<dim3(16, 16, Bn), 256>>>(unary, weight);
        else
            k_final<<<dim3(16, 16, Bn), 256>>>(unary, weight, out);
    }
}

// round 16
// speedup vs baseline: 2.0598x; 1.0021x over previous
#include <cuda_runtime.h>
#include <math.h>

#define Bn 2
#define Cn 21
#define Hn 512
#define Wn 512
#define HL 128
#define WL 128
#define Kn 11
#define SPANn 5
#define KKn 121

#define PP 144
#define XOFF 5
#define YOFF 8
#define PLANE (PP*PP)

#define GK_TILE 128
#define GK_SMEM_BYTES (KKn * GK_TILE * 4)

__device__ float g_ppad [Bn*Cn*PLANE];
__device__ float g_msg  [Bn*Cn*HL*WL];
__device__ float g_cf   [Bn*3*HL*WL];
__device__ float g_gk   [Bn*16*8*KKn*GK_TILE];

__constant__ float c_wtab[4] = {0.375f, 0.125f, 0.875f, 0.625f};

// ---------------------------------------------------------------------------
__global__ void k_zero() {
    int idx = blockIdx.x * 256 + threadIdx.x;
    if (idx < Bn*Cn*PLANE/4) ((float4*)g_ppad)[idx] = make_float4(0.f,0.f,0.f,0.f);
}

// ---------------------------------------------------------------------------
__global__ void k_pool_img(const float* __restrict__ img, const float* __restrict__ schan) {
    int idx = blockIdx.x * 256 + threadIdx.x;
    if (idx >= Bn*3*HL*WL) return;
    int y = idx & (WL-1);
    int x = (idx >> 7) & (HL-1);
    int c = (idx >> 14) % 3;
    int b = idx / (3*HL*WL);
    const float* src = img + ((b*3 + c)*Hn + x*4)*Wn + y*4;
    float s = 0.f;
    #pragma unroll
    for (int i = 0; i < 4; i++)
        #pragma unroll
        for (int j = 0; j < 4; j++) s += src[i*Wn + j];
    g_cf[idx] = s * (schan[0] * 0.0625f);
}

// ---------------------------------------------------------------------------
// gauss kernel, tiled per 8x16 pixel block (exact R9)
__global__ void k_gauss(const float* __restrict__ pos_sdims,
                        const float* __restrict__ pos_compat,
                        const float* __restrict__ col_compat) {
    __shared__ float cf_s[3][18*26];
    __shared__ float pos_s[KKn];
    int tyi = blockIdx.x, txi = blockIdx.y, b = blockIdx.z;
    int t = threadIdx.x;
    int x0 = txi*8 - SPANn, y0 = tyi*16 - SPANn;
    if (t < KKn) {
        int i = t / 11, j = t - i*11;
        int dx = i - SPANn, dy = j - SPANn;
        float sd4 = 4.f * pos_sdims[0];
        float dpos2 = sd4*sd4 * (float)(dx*dx + dy*dy);
        pos_s[t] = pos_compat[0] * __expf(-0.5f*dpos2);
    }
    for (int i = t; i < 3*468; i += 128) {
        int c = i / 468, rem = i % 468;
        int xx = x0 + rem/26, yy = y0 + rem%26;
        float v = 0.f;
        if ((unsigned)xx < HL && (unsigned)yy < WL)
            v = g_cf[((b*3 + c)*HL + xx)*WL + yy];
        cf_s[c][rem] = v;
    }
    __syncthreads();
    int px = t >> 4, py = t & 15;
    int ctr = (px + SPANn)*26 + (py + SPANn);
    float c0 = cf_s[0][ctr], c1 = cf_s[1][ctr], c2 = cf_s[2][ctr];
    float cc = col_compat[0];
    int gx = txi*8 + px, gy = tyi*16 + py;
    float* outb = g_gk + (size_t)(((b*16 + txi)*8 + tyi)*KKn)*GK_TILE + t;
    #pragma unroll 1
    for (int ij = 0; ij < KKn; ij++) {
        int i = ij / 11, j = ij - i*11;
        int dx = i - SPANn, dy = j - SPANn;
        bool valid = ((unsigned)(gx + dx) < HL) && ((unsigned)(gy + dy) < WL);
        int si = (px + i)*26 + (py + j);
        float d0 = cf_s[0][si] - c0;
        float d1 = cf_s[1][si] - c1;
        float d2 = cf_s[2][si] - c2;
        float dcol2 = d0*d0 + d1*d1 + d2*d2;
        float gval = valid ? (pos_s[ij] + cc * __expf(-0.5f*dcol2)) : 0.f;
        outb[ij*GK_TILE] = gval;
    }
}

// ---------------------------------------------------------------------------
// 3) pooled init pred; 4-way partial reductions + __logf
__global__ void k_init(const float* __restrict__ unary) {
    int b = blockIdx.z;
    int w = threadIdx.x >> 5, l = threadIdx.x & 31;
    int x0 = blockIdx.y*32 + w*4;
    int Y  = blockIdx.x*32 + l;
    const float* up = unary + ((size_t)(b*Cn)*Hn + x0)*Wn + Y;
    float pool[Cn];
    #pragma unroll
    for (int c = 0; c < Cn; c++) pool[c] = 0.f;
    #pragma unroll
    for (int r = 0; r < 4; r++) {
        float u[Cn];
        float m0 = -1e30f, m1 = -1e30f, m2 = -1e30f, m3 = -1e30f;
        #pragma unroll
        for (int c = 0; c < Cn; c++) {
            u[c] = __ldg(up + (size_t)c*Hn*Wn + r*Wn);
            if ((c & 3) == 0) m0 = fmaxf(m0, u[c]);
            else if ((c & 3) == 1) m1 = fmaxf(m1, u[c]);
            else if ((c & 3) == 2) m2 = fmaxf(m2, u[c]);
            else m3 = fmaxf(m3, u[c]);
        }
        float m = fmaxf(fmaxf(m0, m1), fmaxf(m2, m3));
        float s0 = 0.f, s1 = 0.f, s2 = 0.f, s3 = 0.f;
        #pragma unroll
        for (int c = 0; c < Cn; c++) {
            float e = __expf(u[c] - m);
            if ((c & 3) == 0) s0 += e;
            else if ((c & 3) == 1) s1 += e;
            else if ((c & 3) == 2) s2 += e;
            else s3 += e;
        }
        float lse = m + __logf((s0 + s1) + (s2 + s3));
        #pragma unroll
        for (int c = 0; c < Cn; c++) pool[c] += u[c] - lse;
    }
    int xp = (x0 >> 2) + XOFF;
    int yp = (Y  >> 2) + YOFF;
    #pragma unroll
    for (int c = 0; c < Cn; c++) {
        float r = pool[c];
        r += __shfl_xor_sync(0xffffffffu, r, 1);
        r += __shfl_xor_sync(0xffffffffu, r, 2);
        if ((l & 3) == 0)
            g_ppad[((size_t)(b*Cn + c)*PP + xp)*PP + yp] = r * 0.0625f;
    }
}

// ---------------------------------------------------------------------------
// 4) message passing (exact R15: software-pipelined)
__global__ __launch_bounds__(224, 2) void k_msg() {
    extern __shared__ float gk_s[];           // [121][128]
    const int t = threadIdx.x;
    const int b = blockIdx.z;
    const int tyi = blockIdx.x, txi = blockIdx.y;
    const int chunk = t >> 5, lane = t & 31;
    const int xrow = lane >> 2, yg = lane & 3;
    const int pxg = txi*8 + xrow;
    const int Yb  = tyi*16 + yg*4;
    const float* gbase = g_gk + (size_t)(((b*16 + txi)*8 + tyi)*KKn)*GK_TILE;

    {
        const float4* src = (const float4*)gbase;
        #pragma unroll 4
        for (int idx = t; idx < KKn*32; idx += 224)
            ((float4*)gk_s)[idx] = __ldg(src + idx);
    }
    __syncthreads();

    float acc[3][4];
    #pragma unroll
    for (int c = 0; c < 3; c++)
        #pragma unroll
        for (int k = 0; k < 4; k++) acc[c][k] = 0.f;

    const int pix = lane*4;
    const float4* pb[3];
    #pragma unroll
    for (int c = 0; c < 3; c++)
        pb[c] = (const float4*)(g_ppad +
            ((size_t)(b*Cn + chunk*3 + c)*PP + pxg)*PP + Yb);

    float4 st[2][3][5];
    #pragma unroll
    for (int c = 0; c < 3; c++)
        #pragma unroll
        for (int q = 0; q < 5; q++)
            st[0][c][q] = __ldg(pb[c] + q);

    #pragma unroll
    for (int i = 0; i < 11; i++) {
        const int cur = i & 1, nxt = cur ^ 1;
        if (i < 10) {
            #pragma unroll
            for (int c = 0; c < 3; c++)
                #pragma unroll
                for (int q = 0; q < 5; q++)
                    st[nxt][c][q] = __ldg(pb[c] + (size_t)(i+1)*(PP/4) + q);
        }
        float pr[3][20];
        #pragma unroll
        for (int c = 0; c < 3; c++)
            #pragma unroll
            for (int q = 0; q < 5; q++) {
                pr[c][q*4+0] = st[cur][c][q].x;
                pr[c][q*4+1] = st[cur][c][q].y;
                pr[c][q*4+2] = st[cur][c][q].z;
                pr[c][q*4+3] = st[cur][c][q].w;
            }
        const float* gs = gk_s + i*11*GK_TILE + pix;
        #pragma unroll
        for (int j = 0; j < 11; j++) {
            float4 gv = *(const float4*)(gs + j*GK_TILE);
            #pragma unroll
            for (int c = 0; c < 3; c++) {
                acc[c][0] += gv.x * pr[c][j + 3];
                acc[c][1] += gv.y * pr[c][j + 4];
                acc[c][2] += gv.z * pr[c][j + 5];
                acc[c][3] += gv.w * pr[c][j + 6];
            }
        }
    }

    #pragma unroll
    for (int c = 0; c < 3; c++) {
        float* mp = g_msg + ((size_t)(b*Cn + chunk*3 + c)*HL + pxg)*WL + Yb;
        *(float4*)mp = make_float4(acc[c][0], acc[c][1], acc[c][2], acc[c][3]);
    }
}

// ---------------------------------------------------------------------------
// 5) fused iter; 4-way partial reductions
__global__ void k_iter(const float* __restrict__ unary, const float* __restrict__ weight) {
    __shared__ float m_s[Cn*100];   // [c][10][10]
    int b = blockIdx.z;
    int t = threadIdx.x, w = t >> 5, l = t & 31;
    int lx0 = blockIdx.y*8 - 1, ly0 = blockIdx.x*8 - 1;
    for (int i = t; i < Cn*100; i += 256) {
        int c = i / 100, rem = i % 100;
        int xx = lx0 + rem/10; xx = max(0, min(HL-1, xx));
        int yy = ly0 + rem%10; yy = max(0, min(WL-1, yy));
        m_s[i] = g_msg[((b*Cn + c)*HL + xx)*WL + yy];
    }
    __syncthreads();
    int x0 = blockIdx.y*32 + w*4;
    int Y  = blockIdx.x*32 + l;
    const float* up = unary + ((size_t)(b*Cn)*Hn + x0)*Wn + Y;
    float wgt = weight[0], uw = 1.f - wgt;
    int ry = l & 3;
    float wy0 = c_wtab[ry], wy1 = 1.f - wy0;
    int yA = (l >> 2) + 1 + ((ry < 2) ? -1 : 0);
    float pool[Cn];
    #pragma unroll
    for (int c = 0; c < Cn; c++) pool[c] = 0.f;
    #pragma unroll
    for (int r = 0; r < 4; r++) {
        float wx0 = c_wtab[r], wx1 = 1.f - wx0;
        int xA = w + 1 + ((r < 2) ? -1 : 0);
        int base = xA*10 + yA;
        float v[Cn];
        float m0 = -1e30f, m1 = -1e30f, m2 = -1e30f, m3 = -1e30f;
        #pragma unroll
        for (int c = 0; c < Cn; c++) {
            const float* mc = m_s + c*100 + base;
            float mu = wx0*(wy0*mc[0] + wy1*mc[1]) + wx1*(wy0*mc[10] + wy1*mc[11]);
            float vv = uw * __ldg(up + (size_t)c*Hn*Wn + r*Wn) + wgt * mu;
            v[c] = vv;
            if ((c & 3) == 0) m0 = fmaxf(m0, vv);
            else if ((c & 3) == 1) m1 = fmaxf(m1, vv);
            else if ((c & 3) == 2) m2 = fmaxf(m2, vv);
            else m3 = fmaxf(m3, vv);
        }
        float mmax = fmaxf(fmaxf(m0, m1), fmaxf(m2, m3));
        float s0 = 0.f, s1 = 0.f, s2 = 0.f, s3 = 0.f;
        #pragma unroll
        for (int c = 0; c < Cn; c++) {
            v[c] = __expf(v[c] - mmax);
            if ((c & 3) == 0) s0 += v[c];
            else if ((c & 3) == 1) s1 += v[c];
            else if ((c & 3) == 2) s2 += v[c];
            else s3 += v[c];
        }
        float inv = 1.f / ((s0 + s1) + (s2 + s3));
        #pragma unroll
        for (int c = 0; c < Cn; c++) pool[c] += v[c] * inv;
    }
    int xp = (x0 >> 2) + XOFF;
    int yp = (Y  >> 2) + YOFF;
    #pragma unroll
    for (int c = 0; c < Cn; c++) {
        float r = pool[c];
        r += __shfl_xor_sync(0xffffffffu, r, 1);
        r += __shfl_xor_sync(0xffffffffu, r, 2);
        if ((l & 3) == 0)
            g_ppad[((size_t)(b*Cn + c)*PP + xp)*PP + yp] = r * 0.0625f;
    }
}

// ---------------------------------------------------------------------------
// 6) final; 4-way partial reductions + __logf
__global__ void k_final(const float* __restrict__ unary, const float* __restrict__ weight,
                        float* __restrict__ out) {
    __shared__ float m_s[Cn*100];
    int b = blockIdx.z;
    int t = threadIdx.x, w = t >> 5, l = t & 31;
    int lx0 = blockIdx.y*8 - 1, ly0 = blockIdx.x*8 - 1;
    for (int i = t; i < Cn*100; i += 256) {
        int c = i / 100, rem = i % 100;
        int xx = lx0 + rem/10; xx = max(0, min(HL-1, xx));
        int yy = ly0 + rem%10; yy = max(0, min(WL-1, yy));
        m_s[i] = g_msg[((b*Cn + c)*HL + xx)*WL + yy];
    }
    __syncthreads();
    int x0 = blockIdx.y*32 + w*4;
    int Y  = blockIdx.x*32 + l;
    const float* up   = unary + ((size_t)(b*Cn)*Hn + x0)*Wn + Y;
    float*       outp = out   + ((size_t)(b*Cn)*Hn + x0)*Wn + Y;
    float wgt = weight[0], uw = 1.f - wgt;
    int ry = l & 3;
    float wy0 = c_wtab[ry], wy1 = 1.f - wy0;
    int yA = (l >> 2) + 1 + ((ry < 2) ? -1 : 0);
    #pragma unroll
    for (int r = 0; r < 4; r++) {
        float wx0 = c_wtab[r], wx1 = 1.f - wx0;
        int xA = w + 1 + ((r < 2) ? -1 : 0);
        int base = xA*10 + yA;
        float u[Cn];
        float m0 = -1e30f, m1 = -1e30f, m2 = -1e30f, m3 = -1e30f;
        #pragma unroll
        for (int c = 0; c < Cn; c++) {
            u[c] = __ldg(up + (size_t)c*Hn*Wn + r*Wn);
            if ((c & 3) == 0) m0 = fmaxf(m0, u[c]);
            else if ((c & 3) == 1) m1 = fmaxf(m1, u[c]);
            else if ((c & 3) == 2) m2 = fmaxf(m2, u[c]);
            else m3 = fmaxf(m3, u[c]);
        }
        float m = fmaxf(fmaxf(m0, m1), fmaxf(m2, m3));
        float s0 = 0.f, s1 = 0.f, s2 = 0.f, s3 = 0.f;
        #pragma unroll
        for (int c = 0; c < Cn; c++) {
            float e = __expf(u[c] - m);
            if ((c & 3) == 0) s0 += e;
            else if ((c & 3) == 1) s1 += e;
            else if ((c & 3) == 2) s2 += e;
            else s3 += e;
        }
        float lse = m + __logf((s0 + s1) + (s2 + s3));
        #pragma unroll
        for (int c = 0; c < Cn; c++) {
            const float* mc = m_s + c*100 + base;
            float mu = wx0*(wy0*mc[0] + wy1*mc[1]) + wx1*(wy0*mc[10] + wy1*mc[11]);
            outp[(size_t)c*Hn*Wn + r*Wn] = uw * (u[c] - lse) + wgt * mu;
        }
    }
}

// ---------------------------------------------------------------------------
extern "C" void kernel_launch(void* const* d_in, const int* in_sizes, int n_in,
                              void* d_out, int out_size) {
    const float* unary      = (const float*)d_in[0];
    const float* img        = (const float*)d_in[1];
    const float* pos_sdims  = (const float*)d_in[2];
    const float* col_schan  = (const float*)d_in[3];
    const float* pos_compat = (const float*)d_in[4];
    const float* col_compat = (const float*)d_in[5];
    const float* weight     = (const float*)d_in[6];
    float* out = (float*)d_out;

    static int smem_set = 0;
    if (!smem_set) {
        cudaFuncSetAttribute(k_msg, cudaFuncAttributeMaxDynamicSharedMemorySize,
                             GK_SMEM_BYTES);
        smem_set = 1;
    }

    k_zero<<<(Bn*Cn*PLANE/4 + 255)/256, 256>>>();
    k_pool_img<<<(Bn*3*HL*WL + 255)/256, 256>>>(img, col_schan);
    k_gauss<<<dim3(8, 16, Bn), 128>>>(pos_sdims, pos_compat, col_compat);
    k_init<<<dim3(16, 16, Bn), 256>>>(unary);
    for (int it = 0; it < 5; it++) {
        k_msg<<<dim3(8, 16, Bn), 224, GK_SMEM_BYTES>>>();
        if (it < 4)
            k_iter<<<dim3(16, 16, Bn), 256>>>(unary, weight);
        else
            k_final<<<dim3(16, 16, Bn), 256>>>(unary, weight, out);
    }
}